// round 16
// baseline (speedup 1.0000x reference)
#include <cuda_runtime.h>
#include <math.h>
#include <mma.h>

using namespace nvcuda;

#define NN 50000
#define NN_PAD 50048   // 391 * 128
#define NE 800000
#define H 128
#define H3 384
#define NB 196         // scan blocks: 196*256 = 50176 >= NN

// rounded-weight scratch offsets (floats)
#define S1 16384
#define S3 49152
#define OFF_WP1 0
#define OFF_WP2 (S1)
#define OFF_WG0 (2*S1)
#define OFF_WG1 (3*S1)
#define OFF_WIH0 (4*S1)
#define OFF_WHH0 (4*S1 + S3)
#define OFF_WIH1 (4*S1 + 2*S3)
#define OFF_WHH1 (4*S1 + 3*S3)
#define WR_TOTAL (4*S1 + 4*S3)

// ---------------- device scratch (no allocs allowed) ----------------
__device__ float g_h0[NN_PAD * H];
__device__ float g_h1[NN_PAD * H];
__device__ float g_hw[NN_PAD * H];
__device__ float g_gcn[NN_PAD * H];
__device__ float g_gi[NN_PAD * H3];
__device__ float g_gh[NN_PAD * H3];
__device__ float g_wr[WR_TOTAL];
__device__ float g_dinv[NN];
__device__ int   g_cnt[NN];
__device__ int   g_cur[NN];
__device__ int   g_rowptr[NN + 1];
__device__ int   g_bsum[256];
__device__ int2  g_edge[NE];

__device__ __forceinline__ float tf32r(float x) { return wmma::__float_to_tf32(x); }

// ---------------- cp.async helpers ----------------
__device__ __forceinline__ void cp_async16(void* smem, const void* gmem, bool pred)
{
    unsigned saddr = (unsigned)__cvta_generic_to_shared(smem);
    int sz = pred ? 16 : 0;
    asm volatile("cp.async.cg.shared.global [%0], [%1], 16, %2;\n"
                 :: "r"(saddr), "l"(gmem), "r"(sz));
}
#define CP_COMMIT() asm volatile("cp.async.commit_group;\n" ::: "memory")
#define CP_WAIT1()  asm volatile("cp.async.wait_group 1;\n" ::: "memory")

// ---------------- tf32 GEMM, 2-stage cp.async double buffer ----------------
// BM=BN=128, BK=16, 256 threads (8 warps 2x4), warp tile 64x32.
// Operands MUST be pre-rounded to tf32 (cp.async copies raw bits).
#define BKK 16
#define ASTR 20
#define BSTR 132

__device__ __forceinline__ void tgemm_body(
    const float* __restrict__ A, const float* __restrict__ B,
    float* __restrict__ C, const float* __restrict__ bias,
    int M, int Ncol, int row0, int col0)
{
    __shared__ float As[2][128][ASTR];
    __shared__ float Bs[2][BKK][BSTR];
    const int tid = threadIdx.x;
    const int warp = tid >> 5;
    const int lane = tid & 31;
    const int wr = warp >> 2;         // 0..1
    const int wc = warp & 3;          // 0..3

    wmma::fragment<wmma::accumulator, 16, 16, 8, float> acc[4][2];
#pragma unroll
    for (int i = 0; i < 4; i++)
#pragma unroll
        for (int j = 0; j < 2; j++)
            wmma::fill_fragment(acc[i][j], 0.0f);

    auto prefetch = [&](int k0, int st) {
#pragma unroll
        for (int t = 0; t < 2; t++) {          // A: 128x16 = 512 float4
            int idx = tid + t * 256;
            int r = idx >> 2;
            int q = idx & 3;
            int gr = row0 + r;
            bool p = gr < M;
            const float* src = A + (size_t)(p ? gr : 0) * 128 + k0 + q * 4;
            cp_async16(&As[st][r][q * 4], src, p);
        }
#pragma unroll
        for (int t = 0; t < 2; t++) {          // B: 16x128 = 512 float4
            int idx = tid + t * 256;
            int r = idx >> 5;
            int q = idx & 31;
            cp_async16(&Bs[st][r][q * 4], &B[(size_t)(k0 + r) * Ncol + col0 + q * 4], true);
        }
    };

    prefetch(0, 0);
    CP_COMMIT();
    prefetch(BKK, 1);
    CP_COMMIT();

#pragma unroll
    for (int kt = 0; kt < 8; kt++) {
        int st = kt & 1;
        CP_WAIT1();                    // stage kt complete (newest pending = kt+1)
        __syncthreads();
#pragma unroll
        for (int kk = 0; kk < BKK; kk += 8) {
            wmma::fragment<wmma::matrix_a, 16, 16, 8, wmma::precision::tf32, wmma::row_major> af[4];
            wmma::fragment<wmma::matrix_b, 16, 16, 8, wmma::precision::tf32, wmma::row_major> bf[2];
#pragma unroll
            for (int i = 0; i < 4; i++)
                wmma::load_matrix_sync(af[i], &As[st][wr * 64 + i * 16][kk], ASTR);
#pragma unroll
            for (int j = 0; j < 2; j++)
                wmma::load_matrix_sync(bf[j], &Bs[st][kk][wc * 32 + j * 16], BSTR);
#pragma unroll
            for (int i = 0; i < 4; i++)
#pragma unroll
                for (int j = 0; j < 2; j++)
                    wmma::mma_sync(acc[i][j], af[i], bf[j], acc[i][j]);
        }
        __syncthreads();               // all warps done reading stage st
        if (kt < 6) prefetch((kt + 2) * BKK, st);
        CP_COMMIT();                   // empty group when kt>=6 keeps count aligned
    }

    if (bias == nullptr) {
        // fast path: raw fp32 store (padded rows)
#pragma unroll
        for (int i = 0; i < 4; i++)
#pragma unroll
            for (int j = 0; j < 2; j++) {
                int r = row0 + wr * 64 + i * 16;
                int c = col0 + wc * 32 + j * 16;
                wmma::store_matrix_sync(&C[(size_t)r * Ncol + c], acc[i][j], Ncol, wmma::mem_row_major);
            }
    } else {
        // staged epilogue: + bias, leaky relu, round to tf32
        __syncthreads();
        float* stage = &As[0][0][0] + warp * 256;   // 1KB per warp
        int lr = lane >> 1;
        int lc = (lane & 1) * 8;
#pragma unroll
        for (int i = 0; i < 4; i++)
#pragma unroll
            for (int j = 0; j < 2; j++) {
                wmma::store_matrix_sync(stage, acc[i][j], 16, wmma::mem_row_major);
                __syncwarp();
                float4 u0 = *reinterpret_cast<float4*>(stage + lr * 16 + lc);
                float4 u1 = *reinterpret_cast<float4*>(stage + lr * 16 + lc + 4);
                int gr = row0 + wr * 64 + i * 16 + lr;
                int gc = col0 + wc * 32 + j * 16 + lc;
                float4 b0 = *reinterpret_cast<const float4*>(bias + gc);
                float4 b1 = *reinterpret_cast<const float4*>(bias + gc + 4);
                u0.x += b0.x; u0.y += b0.y; u0.z += b0.z; u0.w += b0.w;
                u1.x += b1.x; u1.y += b1.y; u1.z += b1.z; u1.w += b1.w;
                u0.x = u0.x >= 0.f ? u0.x : 0.01f * u0.x;
                u0.y = u0.y >= 0.f ? u0.y : 0.01f * u0.y;
                u0.z = u0.z >= 0.f ? u0.z : 0.01f * u0.z;
                u0.w = u0.w >= 0.f ? u0.w : 0.01f * u0.w;
                u1.x = u1.x >= 0.f ? u1.x : 0.01f * u1.x;
                u1.y = u1.y >= 0.f ? u1.y : 0.01f * u1.y;
                u1.z = u1.z >= 0.f ? u1.z : 0.01f * u1.z;
                u1.w = u1.w >= 0.f ? u1.w : 0.01f * u1.w;
                u0.x = tf32r(u0.x); u0.y = tf32r(u0.y); u0.z = tf32r(u0.z); u0.w = tf32r(u0.w);
                u1.x = tf32r(u1.x); u1.y = tf32r(u1.y); u1.z = tf32r(u1.z); u1.w = tf32r(u1.w);
                *reinterpret_cast<float4*>(&C[(size_t)gr * Ncol + gc]) = u0;
                *reinterpret_cast<float4*>(&C[(size_t)gr * Ncol + gc + 4]) = u1;
                __syncwarp();
            }
    }
}

__global__ void __launch_bounds__(256, 2) tgemm_k(
    const float* __restrict__ A, const float* __restrict__ B,
    float* __restrict__ C, const float* __restrict__ bias, int M, int Ncol)
{
    tgemm_body(A, B, C, bias, M, Ncol, blockIdx.y * 128, blockIdx.x * 128);
}

__global__ void __launch_bounds__(256, 2) tgemm2_k(
    const float* __restrict__ A0, const float* __restrict__ B0, float* __restrict__ C0,
    const float* __restrict__ A1, const float* __restrict__ B1, float* __restrict__ C1,
    int M, int Ncol)
{
    if (blockIdx.z == 0)
        tgemm_body(A0, B0, C0, nullptr, M, Ncol, blockIdx.y * 128, blockIdx.x * 128);
    else
        tgemm_body(A1, B1, C1, nullptr, M, Ncol, blockIdx.y * 128, blockIdx.x * 128);
}

// ---------------- round all 8 weight matrices to tf32 ----------------
__global__ void roundw_k(const float* __restrict__ w0, const float* __restrict__ w1,
                         const float* __restrict__ w2, const float* __restrict__ w3,
                         const float* __restrict__ w4, const float* __restrict__ w5,
                         const float* __restrict__ w6, const float* __restrict__ w7,
                         float* __restrict__ dst)
{
    int i = blockIdx.x * blockDim.x + threadIdx.x;
    if (i >= WR_TOTAL) return;
    float v;
    if (i < 4 * S1) {
        int k = i / S1, r = i - k * S1;
        const float* s = (k == 0) ? w0 : (k == 1) ? w1 : (k == 2) ? w2 : w3;
        v = s[r];
    } else {
        int j = i - 4 * S1;
        int k = j / S3, r = j - k * S3;
        const float* s = (k == 0) ? w4 : (k == 1) ? w5 : (k == 2) ? w6 : w7;
        v = s[r];
    }
    dst[i] = tf32r(v);
}

// ---------------- CSR build ----------------
__global__ void zero_int_k(int* __restrict__ p, int n)
{
    int i = blockIdx.x * blockDim.x + threadIdx.x;
    if (i < n) p[i] = 0;
}

__global__ void count_k(const int* __restrict__ dst, int* __restrict__ cnt)
{
    int i = blockIdx.x * blockDim.x + threadIdx.x;
    if (i < NE) {
        int d = dst[i];
        if ((unsigned)d < NN) atomicAdd(&cnt[d], 1);
    }
}

__global__ void __launch_bounds__(256) partial_k(const int* __restrict__ cnt,
                                                 int* __restrict__ bsum)
{
    int b = blockIdx.x, t = threadIdx.x;
    int i = b * 256 + t;
    int v = (i < NN) ? cnt[i] : 0;
#pragma unroll
    for (int o = 16; o; o >>= 1) v += __shfl_xor_sync(0xFFFFFFFFu, v, o);
    __shared__ int ws[8];
    if ((t & 31) == 0) ws[t >> 5] = v;
    __syncthreads();
    if (t == 0) {
        int s = 0;
#pragma unroll
        for (int w = 0; w < 8; w++) s += ws[w];
        bsum[b] = s;
    }
}

__global__ void __launch_bounds__(256) scanb_k(int* __restrict__ bsum)
{
    __shared__ int s[256];
    int t = threadIdx.x;
    int v = (t < NB) ? bsum[t] : 0;
    s[t] = v;
    __syncthreads();
    for (int off = 1; off < 256; off <<= 1) {
        int u = (t >= off) ? s[t - off] : 0;
        __syncthreads();
        s[t] += u;
        __syncthreads();
    }
    bsum[t] = s[t] - v;   // exclusive
}

__global__ void __launch_bounds__(256) rowptr_k(const int* __restrict__ cnt,
                                                const int* __restrict__ bsum,
                                                int* __restrict__ rowptr,
                                                int* __restrict__ cur,
                                                float* __restrict__ dinv)
{
    __shared__ int s[256];
    int b = blockIdx.x, t = threadIdx.x;
    int i = b * 256 + t;
    int v = (i < NN) ? cnt[i] : 0;
    s[t] = v;
    __syncthreads();
    for (int off = 1; off < 256; off <<= 1) {
        int u = (t >= off) ? s[t - off] : 0;
        __syncthreads();
        s[t] += u;
        __syncthreads();
    }
    int base = bsum[b];
    if (i < NN) {
        int rp = base + s[t] - v;
        rowptr[i] = rp;
        cur[i] = rp;
        dinv[i] = rsqrtf((float)v + 1.0f);
    }
    if (b == NB - 1 && t == 255) rowptr[NN] = base + s[t];
}

__global__ void fill_k(const int* __restrict__ src, const int* __restrict__ dst,
                       const float* __restrict__ dinv, int* __restrict__ cur,
                       int2* __restrict__ edge)
{
    int i = blockIdx.x * blockDim.x + threadIdx.x;
    if (i >= NE) return;
    int s = src[i], d = dst[i];
    if ((unsigned)s >= NN || (unsigned)d >= NN) return;
    float nrm = dinv[s] * dinv[d];
    int pos = atomicAdd(&cur[d], 1);
    edge[pos] = make_int2(s, __float_as_int(nrm));
}

// ---------------- fused aggregate + self-loop + bias + lrelu + tf32 round ----------------
__global__ void __launch_bounds__(256) agg_k(
    const int* __restrict__ rowptr, const int2* __restrict__ edge,
    const float* __restrict__ hw, const float* __restrict__ dinv,
    const float* __restrict__ bias, float* __restrict__ out)
{
    int warp = (blockIdx.x * blockDim.x + threadIdx.x) >> 5;
    int lane = threadIdx.x & 31;
    if (warp >= NN) return;
    int beg = rowptr[warp], end = rowptr[warp + 1];
    float di = dinv[warp];
    float d2 = di * di;
    float4 self = reinterpret_cast<const float4*>(&hw[(size_t)warp * H])[lane];
    float4 acc;
    acc.x = self.x * d2; acc.y = self.y * d2; acc.z = self.z * d2; acc.w = self.w * d2;
    for (int e = beg; e < end; e++) {
        int2 ed = __ldg(&edge[e]);
        float nrm = __int_as_float(ed.y);
        float4 v = __ldg(&reinterpret_cast<const float4*>(&hw[(size_t)ed.x * H])[lane]);
        acc.x = fmaf(v.x, nrm, acc.x);
        acc.y = fmaf(v.y, nrm, acc.y);
        acc.z = fmaf(v.z, nrm, acc.z);
        acc.w = fmaf(v.w, nrm, acc.w);
    }
    float4 b = reinterpret_cast<const float4*>(bias)[lane];
    acc.x += b.x; acc.y += b.y; acc.z += b.z; acc.w += b.w;
    acc.x = acc.x >= 0.f ? acc.x : 0.01f * acc.x;
    acc.y = acc.y >= 0.f ? acc.y : 0.01f * acc.y;
    acc.z = acc.z >= 0.f ? acc.z : 0.01f * acc.z;
    acc.w = acc.w >= 0.f ? acc.w : 0.01f * acc.w;
    acc.x = tf32r(acc.x); acc.y = tf32r(acc.y); acc.z = tf32r(acc.z); acc.w = tf32r(acc.w);
    reinterpret_cast<float4*>(&out[(size_t)warp * H])[lane] = acc;
}

// ---------------- GRU (biases folded) + head ----------------
__device__ __forceinline__ float sigm(float x) { return 1.0f / (1.0f + expf(-x)); }

// outr (optional): tf32-rounded copy for the next layer's GEMM
__global__ void gru_k(const float* __restrict__ gi, const float* __restrict__ gh,
                      const float* __restrict__ bih, const float* __restrict__ bhh,
                      const float* __restrict__ prev, float* __restrict__ out,
                      float* __restrict__ outr)
{
    int i = blockIdx.x * blockDim.x + threadIdx.x;
    if (i >= NN * H) return;
    int nrow = i / H;
    int c = i % H;
    size_t base = (size_t)nrow * H3 + c;
    float ir = gi[base]          + bih[c];
    float iz = gi[base + H]      + bih[c + H];
    float inn = gi[base + 2 * H] + bih[c + 2 * H];
    float hr = gh[base]          + bhh[c];
    float hz = gh[base + H]      + bhh[c + H];
    float hn = gh[base + 2 * H]  + bhh[c + 2 * H];
    float r = sigm(ir + hr);
    float z = sigm(iz + hz);
    float nn_ = tanhf(inn + r * hn);
    float o = (1.0f - z) * nn_ + z * prev[i];
    out[i] = o;
    if (outr) outr[i] = tf32r(o);
}

__global__ void post_k(const float* __restrict__ h, const float* __restrict__ w,
                       const float* __restrict__ b, float* __restrict__ out)
{
    int gwarp = (blockIdx.x * blockDim.x + threadIdx.x) >> 5;
    int lane = threadIdx.x & 31;
    if (gwarp >= NN) return;
    float4 wv = reinterpret_cast<const float4*>(w)[lane];
    float4 hv = reinterpret_cast<const float4*>(&h[(size_t)gwarp * H])[lane];
    float s = hv.x * wv.x + hv.y * wv.y + hv.z * wv.z + hv.w * wv.w;
#pragma unroll
    for (int o = 16; o; o >>= 1) s += __shfl_xor_sync(0xFFFFFFFFu, s, o);
    if (lane == 0) out[gwarp] = s + b[0];
}

// ---------------- launch ----------------
extern "C" void kernel_launch(void* const* d_in, const int* in_sizes, int n_in,
                              void* d_out, int out_size)
{
    const float* x        = (const float*)d_in[0];
    const int*   ei       = (const int*)d_in[1];
    const float* w_pre1   = (const float*)d_in[2];
    const float* b_pre1   = (const float*)d_in[3];
    const float* w_pre2   = (const float*)d_in[4];
    const float* b_pre2   = (const float*)d_in[5];
    const float* w_gcn0   = (const float*)d_in[6];
    const float* b_gcn0   = (const float*)d_in[7];
    const float* w_gcn1   = (const float*)d_in[8];
    const float* b_gcn1   = (const float*)d_in[9];
    const float* wih0     = (const float*)d_in[10];
    const float* whh0     = (const float*)d_in[11];
    const float* bih0     = (const float*)d_in[12];
    const float* bhh0     = (const float*)d_in[13];
    const float* wih1     = (const float*)d_in[14];
    const float* whh1     = (const float*)d_in[15];
    const float* bih1     = (const float*)d_in[16];
    const float* bhh1     = (const float*)d_in[17];
    const float* prev0    = (const float*)d_in[18];
    const float* prev1    = (const float*)d_in[19];
    const float* w_post   = (const float*)d_in[20];
    const float* b_post   = (const float*)d_in[21];

    float* out  = (float*)d_out;
    float* emb0 = out + NN;
    float* emb1 = emb0 + (size_t)NN * H;

    float *h0, *h1, *hw, *gcn, *gi, *gh, *wrr, *dinv;
    int *cnt, *cur, *rowptr, *bsum;
    int2 *edge;
    cudaGetSymbolAddress((void**)&h0, g_h0);
    cudaGetSymbolAddress((void**)&h1, g_h1);
    cudaGetSymbolAddress((void**)&hw, g_hw);
    cudaGetSymbolAddress((void**)&gcn, g_gcn);
    cudaGetSymbolAddress((void**)&gi, g_gi);
    cudaGetSymbolAddress((void**)&gh, g_gh);
    cudaGetSymbolAddress((void**)&wrr, g_wr);
    cudaGetSymbolAddress((void**)&dinv, g_dinv);
    cudaGetSymbolAddress((void**)&cnt, g_cnt);
    cudaGetSymbolAddress((void**)&cur, g_cur);
    cudaGetSymbolAddress((void**)&rowptr, g_rowptr);
    cudaGetSymbolAddress((void**)&bsum, g_bsum);
    cudaGetSymbolAddress((void**)&edge, g_edge);

    const int* e_src = ei;
    const int* e_dst = ei + NE;

    dim3 g128(1, NN_PAD / 128);
    dim3 g384x2(3, NN_PAD / 128, 2);
    const int T = 256;

    // rounded weights
    roundw_k<<<(WR_TOTAL + T - 1) / T, T>>>(w_pre1, w_pre2, w_gcn0, w_gcn1,
                                            wih0, whh0, wih1, whh1, wrr);

    // CSR build
    zero_int_k<<<(NN + T - 1) / T, T>>>(cnt, NN);
    count_k<<<(NE + T - 1) / T, T>>>(e_dst, cnt);
    partial_k<<<NB, 256>>>(cnt, bsum);
    scanb_k<<<1, 256>>>(bsum);
    rowptr_k<<<NB, 256>>>(cnt, bsum, rowptr, cur, dinv);
    fill_k<<<(NE + T - 1) / T, T>>>(e_src, e_dst, dinv, cur, edge);

    // pre MLP (bias+lrelu+round fused into GEMM epilogue)
    tgemm_k<<<g128, T>>>(x, wrr + OFF_WP1, h0, b_pre1, NN, H);
    tgemm_k<<<g128, T>>>(h0, wrr + OFF_WP2, h1, b_pre2, NN, H);

    // ---- layer 0 ----
    tgemm_k<<<g128, T>>>(h1, wrr + OFF_WG0, hw, nullptr, NN, H);
    agg_k<<<(NN * 32 + T - 1) / T, T>>>(rowptr, edge, hw, dinv, b_gcn0, gcn);
    tgemm2_k<<<g384x2, T>>>(gcn, wrr + OFF_WIH0, gi, prev0, wrr + OFF_WHH0, gh, NN, H3);
    gru_k<<<(NN * H + T - 1) / T, T>>>(gi, gh, bih0, bhh0, prev0, emb0, h0);

    // ---- layer 1 ----
    tgemm_k<<<g128, T>>>(h0, wrr + OFF_WG1, hw, nullptr, NN, H);
    agg_k<<<(NN * 32 + T - 1) / T, T>>>(rowptr, edge, hw, dinv, b_gcn1, gcn);
    tgemm2_k<<<g384x2, T>>>(gcn, wrr + OFF_WIH1, gi, prev1, wrr + OFF_WHH1, gh, NN, H3);
    gru_k<<<(NN * H + T - 1) / T, T>>>(gi, gh, bih1, bhh1, prev1, emb1, nullptr);

    // post head
    post_k<<<(NN * 32 + T - 1) / T, T>>>(emb1, w_post, b_post, out);
}